// round 7
// baseline (speedup 1.0000x reference)
#include <cuda_runtime.h>
#include <cstdint>
#include <cstddef>

// Problem constants
#define B_  256
#define T_  512
#define I_  64
#define H_  256
#define G_  1024            // 4*H
#define BT_ (B_ * T_)       // 131072

// -------- scratch (device globals; no allocation allowed) --------
__device__ float g_xp[(size_t)BT_ * G_];   // gate pre-activations for current layer
__device__ float g_s0[(size_t)BT_ * H_];   // layer output sequence (ping)
__device__ float g_s1[(size_t)BT_ * H_];   // layer output sequence (pong)

// ---------------- packed f32x2 helpers (PTX-only path) ----------------
__device__ __forceinline__ unsigned long long pack2(float lo, float hi) {
    unsigned long long r;
    asm("mov.b64 %0, {%1, %2};" : "=l"(r)
        : "r"(__float_as_uint(lo)), "r"(__float_as_uint(hi)));
    return r;
}
__device__ __forceinline__ void fma2(unsigned long long& d,
                                     unsigned long long a, unsigned long long b) {
    asm("fma.rn.f32x2 %0, %1, %2, %0;" : "+l"(d) : "l"(a), "l"(b));
}
__device__ __forceinline__ float2 unpack2(unsigned long long v) {
    unsigned lo, hi;
    asm("mov.b64 {%0, %1}, %2;" : "=r"(lo), "=r"(hi) : "l"(v));
    return make_float2(__uint_as_float(lo), __uint_as_float(hi));
}

// =====================================================================
// GEMM: C[M,N] = A[M,K] * B[N,K]^T + bias1[N] (+ bias2[N])
// BM=128, BN=64, BK=16, 256 threads. f32x2 over M-pairs.
// (unchanged from the passing version)
// =====================================================================
__global__ void __launch_bounds__(256, 2)
gemm_abt_bias(const float* __restrict__ A, const float* __restrict__ Bm,
              const float* __restrict__ bias1, const float* __restrict__ bias2,
              float* __restrict__ C, int M, int N, int K)
{
    __shared__ float As[16][128];
    __shared__ float Bs[16][64];

    const int tid = threadIdx.x;
    const int m0  = blockIdx.y * 128;
    const int n0  = blockIdx.x * 64;
    const int ty8 = (tid >> 4) * 8;
    const int tx4 = (tid & 15) * 4;

    unsigned long long acc2[4][4];
#pragma unroll
    for (int p = 0; p < 4; ++p)
#pragma unroll
        for (int j = 0; j < 4; ++j) acc2[p][j] = 0ULL;

    const int ntile = K >> 4;
    for (int kt = 0; kt < ntile; ++kt) {
        const int k0 = kt << 4;
#pragma unroll
        for (int r = 0; r < 2; ++r) {
            int idx = tid + (r << 8);
            int m = idx >> 2, kq = idx & 3;
            float4 v = *(const float4*)&A[(size_t)(m0 + m) * K + k0 + (kq << 2)];
            As[kq * 4 + 0][m] = v.x; As[kq * 4 + 1][m] = v.y;
            As[kq * 4 + 2][m] = v.z; As[kq * 4 + 3][m] = v.w;
        }
        {
            int n = tid >> 2, kq = tid & 3;
            float4 v = *(const float4*)&Bm[(size_t)(n0 + n) * K + k0 + (kq << 2)];
            Bs[kq * 4 + 0][n] = v.x; Bs[kq * 4 + 1][n] = v.y;
            Bs[kq * 4 + 2][n] = v.z; Bs[kq * 4 + 3][n] = v.w;
        }
        __syncthreads();

#pragma unroll
        for (int kk = 0; kk < 16; ++kk) {
            ulonglong2 a01 = *(const ulonglong2*)&As[kk][ty8];
            ulonglong2 a23 = *(const ulonglong2*)&As[kk][ty8 + 4];
            float4 bv = *(const float4*)&Bs[kk][tx4];
            unsigned long long am[4] = {a01.x, a01.y, a23.x, a23.y};
            float br[4] = {bv.x, bv.y, bv.z, bv.w};
#pragma unroll
            for (int j = 0; j < 4; ++j) {
                unsigned long long bp = pack2(br[j], br[j]);
#pragma unroll
                for (int p = 0; p < 4; ++p) fma2(acc2[p][j], am[p], bp);
            }
        }
        __syncthreads();
    }

    float bvv[4];
#pragma unroll
    for (int j = 0; j < 4; ++j) {
        float b = bias1[n0 + tx4 + j];
        if (bias2) b += bias2[n0 + tx4 + j];
        bvv[j] = b;
    }
#pragma unroll
    for (int p = 0; p < 4; ++p) {
        float4 o0, o1;
        float2 u0 = unpack2(acc2[p][0]);
        float2 u1 = unpack2(acc2[p][1]);
        float2 u2 = unpack2(acc2[p][2]);
        float2 u3 = unpack2(acc2[p][3]);
        o0.x = u0.x + bvv[0]; o0.y = u1.x + bvv[1]; o0.z = u2.x + bvv[2]; o0.w = u3.x + bvv[3];
        o1.x = u0.y + bvv[0]; o1.y = u1.y + bvv[1]; o1.z = u2.y + bvv[2]; o1.w = u3.y + bvv[3];
        *(float4*)&C[(size_t)(m0 + ty8 + 2 * p)     * N + n0 + tx4] = o0;
        *(float4*)&C[(size_t)(m0 + ty8 + 2 * p + 1) * N + n0 + tx4] = o1;
    }
}

// =====================================================================
// Recurrent LSTM scan v5: 512 threads, R=2 rows/thread, k-pair-packed W,
// blocked k ownership, h read as u64 pairs (no packing), padded SMEM.
//   grid = 128 CTAs = 16 clusters x 8; cluster owns 16 batch rows.
//   CTA rank owns CTA-local gate rows [0,128): r -> g=r>>5, c=r&31,
//   global row gr = g*256 + rank*32 + c.
//   Thread tid (512): rg = tid>>3 (rows r0=2rg, r0+1), kg = tid&7
//   (owns k in [kg*32, kg*32+32)).  rW[2][16] u64 = k-pairs of each row.
//   h layout: hS[b][k] with 16B pad per 32-k block:
//     off(b,k) = b*292 + (k>>5)*36 + (k&31)   (floats)
//   Dot: per (b,jq): 1 LDS.128 = 2 h k-pairs -> 4 FMA2 into acc[b][row]
//   (each acc u64 = (even-k, odd-k) partial).  Bank-check: lanes
//   (4 rg broadcast x 8 kg) hit banks 4(kg+jq)%32 -> all 32 once.
//   Reduce: hadd then 3x scalar shfl_xor over kg; kg==0 writes STS.64
//   (row-pair) to ex[b][r].  Epilogue: 1 (b,c) per thread.
// =====================================================================
#define KBLK 36                   // 32 k + 4 pad floats per block
#define PB5  (8 * KBLK + 4)       // 292 floats per batch row
#define PE   132

__device__ __forceinline__ float fsig(float x) {
    x = fminf(fmaxf(x, -30.f), 30.f);
    return __fdividef(1.f, 1.f + __expf(-x));
}
__device__ __forceinline__ float ftanh_(float x) {
    x = fminf(fmaxf(x, -15.f), 15.f);
    float e = __expf(-2.f * x);
    return __fdividef(1.f - e, 1.f + e);
}

__global__ void __cluster_dims__(8, 1, 1) __launch_bounds__(512, 1)
lstm_rec(const float* __restrict__ Whh, const float* __restrict__ xpg,
         float* __restrict__ seq_out)
{
    __shared__ __align__(16) float hS[16 * PB5];   // h_{t-1}, blocked+padded
    __shared__ __align__(16) float ex[16 * PE];    // dots: [batch][row]

    const int tid  = threadIdx.x;
    const int rank = blockIdx.x & 7;
    const int b0   = (blockIdx.x >> 3) * 16;

    const int kg = tid & 7;          // k-block owner (k in [kg*32, kg*32+32))
    const int rg = tid >> 3;         // rowgroup 0..63
    const int r0 = rg << 1;          // rows r0, r0+1

    // W rows into registers, packed as k-pairs (natural u64 from global)
    unsigned long long rW[2][16];
#pragma unroll
    for (int r = 0; r < 2; ++r) {
        int rr = r0 + r;
        int gr = ((rr >> 5) << 8) + (rank << 5) + (rr & 31);
        const float* wp = &Whh[(size_t)gr * H_ + (kg << 5)];
#pragma unroll
        for (int q = 0; q < 8; ++q) {
            ulonglong2 v = *(const ulonglong2*)&wp[q << 2];
            rW[r][2 * q]     = v.x;
            rW[r][2 * q + 1] = v.y;
        }
    }

    // zero h buffer (t=0 state, incl. pads)
    for (int idx = tid; idx < 16 * PB5; idx += 512) hS[idx] = 0.f;

    // epilogue mapping: one (batch, col) per thread
    const int eb = tid >> 5, ec = tid & 31;
    float cstt = 0.f;

    __syncthreads();

    for (int t = 0; t < T_; ++t) {
        // ---- stage h_{t-1}: coalesced LDG.128 -> padded-blocked STS.128 ----
        if (t > 0) {
#pragma unroll
            for (int j = 0; j < 2; ++j) {
                int f = tid + (j << 9);
                int b = f >> 6, k0 = (f & 63) << 2;
                float4 v = *(const float4*)&seq_out[((size_t)(b0 + b) * T_ + (t - 1)) * H_ + k0];
                *(float4*)&hS[b * PB5 + (k0 >> 5) * KBLK + (k0 & 31)] = v;
            }
        }
        // prefetch xp (independent of h)
        float xv[4];
#pragma unroll
        for (int g = 0; g < 4; ++g)
            xv[g] = __ldg(&xpg[((size_t)(b0 + eb) * T_ + t) * G_ +
                               (g << 8) + (rank << 5) + ec]);
        __syncthreads();

        // ---- dot over this thread's 32-k block, batches in chunks of 4 ----
        const float* hb = hS + kg * KBLK;
#pragma unroll
        for (int bc = 0; bc < 4; ++bc) {
            unsigned long long acc[4][2];
#pragma unroll
            for (int b = 0; b < 4; ++b) { acc[b][0] = 0ULL; acc[b][1] = 0ULL; }

#pragma unroll
            for (int jq = 0; jq < 8; ++jq) {
#pragma unroll
                for (int b = 0; b < 4; ++b) {
                    ulonglong2 hh = *(const ulonglong2*)&hb[((bc << 2) + b) * PB5 + (jq << 2)];
                    fma2(acc[b][0], rW[0][2 * jq],     hh.x);
                    fma2(acc[b][0], rW[0][2 * jq + 1], hh.y);
                    fma2(acc[b][1], rW[1][2 * jq],     hh.x);
                    fma2(acc[b][1], rW[1][2 * jq + 1], hh.y);
                }
            }

            // hadd (even+odd k) then reduce over 8 kg lanes
#pragma unroll
            for (int b = 0; b < 4; ++b) {
                float2 u0 = unpack2(acc[b][0]);
                float2 u1 = unpack2(acc[b][1]);
                float s0 = u0.x + u0.y;
                float s1 = u1.x + u1.y;
#pragma unroll
                for (int st = 1; st <= 4; st <<= 1) {
                    s0 += __shfl_xor_sync(0xffffffffu, s0, st);
                    s1 += __shfl_xor_sync(0xffffffffu, s1, st);
                }
                if (kg == 0)
                    *(unsigned long long*)&ex[((bc << 2) + b) * PE + r0] = pack2(s0, s1);
            }
        }
        __syncthreads();

        // ---- gates + state update + h write (one (b,c) per thread) ----
        {
            float iv = ex[eb * PE + ec]      + xv[0];
            float fv = ex[eb * PE + 32 + ec] + xv[1];
            float gv = ex[eb * PE + 64 + ec] + xv[2];
            float ov = ex[eb * PE + 96 + ec] + xv[3];
            float ig = fsig(iv), fg = fsig(fv), gg = ftanh_(gv), og = fsig(ov);
            cstt = fg * cstt + ig * gg;
            seq_out[((size_t)(b0 + eb) * T_ + t) * H_ + (rank << 5) + ec] = og * ftanh_(cstt);
        }

        // ---- cluster barrier: release h writes / acquire peers' ----
        asm volatile("barrier.cluster.arrive.aligned;\n\t"
                     "barrier.cluster.wait.aligned;\n\t" ::: "memory");
    }
}

// =====================================================================
// Launcher
// =====================================================================
extern "C" void kernel_launch(void* const* d_in, const int* in_sizes, int n_in,
                              void* d_out, int out_size)
{
    const float* x     = (const float*)d_in[0];
    const float* eWih0 = (const float*)d_in[1];
    const float* eWhh0 = (const float*)d_in[2];
    const float* ebih0 = (const float*)d_in[3];
    const float* ebhh0 = (const float*)d_in[4];
    const float* eWih1 = (const float*)d_in[5];
    const float* eWhh1 = (const float*)d_in[6];
    const float* ebih1 = (const float*)d_in[7];
    const float* ebhh1 = (const float*)d_in[8];
    const float* dWih0 = (const float*)d_in[9];
    const float* dWhh0 = (const float*)d_in[10];
    const float* dbih0 = (const float*)d_in[11];
    const float* dbhh0 = (const float*)d_in[12];
    const float* dWih1 = (const float*)d_in[13];
    const float* dWhh1 = (const float*)d_in[14];
    const float* dbih1 = (const float*)d_in[15];
    const float* dbhh1 = (const float*)d_in[16];
    const float* out_W = (const float*)d_in[17];
    const float* out_b = (const float*)d_in[18];
    float* out = (float*)d_out;

    void* p;
    cudaGetSymbolAddress(&p, g_xp); float* xp = (float*)p;
    cudaGetSymbolAddress(&p, g_s0); float* s0 = (float*)p;
    cudaGetSymbolAddress(&p, g_s1); float* s1 = (float*)p;

    dim3 blk(256);
    dim3 rblk(512);
    dim3 gXP(G_ / 64, BT_ / 128);   // N=1024 tiles x M tiles
    dim3 gPR(I_ / 64, BT_ / 128);   // projection N=64

    // encoder layer 0 (K = I = 64)
    gemm_abt_bias<<<gXP, blk>>>(x, eWih0, ebih0, ebhh0, xp, BT_, G_, I_);
    lstm_rec<<<128, rblk>>>(eWhh0, xp, s0);
    // encoder layer 1 (K = H)
    gemm_abt_bias<<<gXP, blk>>>(s0, eWih1, ebih1, ebhh1, xp, BT_, G_, H_);
    lstm_rec<<<128, rblk>>>(eWhh1, xp, s1);
    // decoder layer 0
    gemm_abt_bias<<<gXP, blk>>>(s1, dWih0, dbih0, dbhh0, xp, BT_, G_, H_);
    lstm_rec<<<128, rblk>>>(dWhh0, xp, s0);
    // decoder layer 1
    gemm_abt_bias<<<gXP, blk>>>(s0, dWih1, dbih1, dbhh1, xp, BT_, G_, H_);
    lstm_rec<<<128, rblk>>>(dWhh1, xp, s1);
    // output projection (N = I = 64, K = H)
    gemm_abt_bias<<<gPR, blk>>>(s1, out_W, out_b, nullptr, out, BT_, I_, H_);
}

// round 11
// speedup vs baseline: 1.0541x; 1.0541x over previous
#include <cuda_runtime.h>
#include <cstdint>
#include <cstddef>

// Problem constants
#define B_  256
#define T_  512
#define I_  64
#define H_  256
#define G_  1024            // 4*H
#define BT_ (B_ * T_)       // 131072

// -------- scratch (device globals; no allocation allowed) --------
__device__ float g_xp[(size_t)BT_ * G_];   // gate pre-activations for current layer
__device__ float g_s0[(size_t)BT_ * H_];   // layer output sequence (ping)
__device__ float g_s1[(size_t)BT_ * H_];   // layer output sequence (pong)

// ---------------- packed f32x2 helpers (PTX-only path) ----------------
__device__ __forceinline__ unsigned long long pack2(float lo, float hi) {
    unsigned long long r;
    asm("mov.b64 %0, {%1, %2};" : "=l"(r)
        : "r"(__float_as_uint(lo)), "r"(__float_as_uint(hi)));
    return r;
}
__device__ __forceinline__ void fma2(unsigned long long& d,
                                     unsigned long long a, unsigned long long b) {
    asm("fma.rn.f32x2 %0, %1, %2, %0;" : "+l"(d) : "l"(a), "l"(b));
}
__device__ __forceinline__ float2 unpack2(unsigned long long v) {
    unsigned lo, hi;
    asm("mov.b64 {%0, %1}, %2;" : "=r"(lo), "=r"(hi) : "l"(v));
    return make_float2(__uint_as_float(lo), __uint_as_float(hi));
}
__device__ __forceinline__ unsigned long long add2(unsigned long long a,
                                                   unsigned long long b) {
    unsigned long long r;
    asm("add.rn.f32x2 %0, %1, %2;" : "=l"(r) : "l"(a), "l"(b));
    return r;
}
__device__ __forceinline__ unsigned long long shflx64(unsigned long long v, int m) {
    unsigned lo, hi;
    asm("mov.b64 {%0, %1}, %2;" : "=r"(lo), "=r"(hi) : "l"(v));
    lo = __shfl_xor_sync(0xffffffffu, lo, m);
    hi = __shfl_xor_sync(0xffffffffu, hi, m);
    unsigned long long r;
    asm("mov.b64 %0, {%1, %2};" : "=l"(r) : "r"(lo), "r"(hi));
    return r;
}
// streaming (evict-first) global load: protects L2 residency of h exchange
__device__ __forceinline__ float ldg_cs(const float* p) {
    float v;
    asm("ld.global.cs.f32 %0, [%1];" : "=f"(v) : "l"(p));
    return v;
}

// =====================================================================
// GEMM: C[M,N] = A[M,K] * B[N,K]^T + bias1[N] (+ bias2[N])
// (unchanged from the passing version)
// =====================================================================
__global__ void __launch_bounds__(256, 2)
gemm_abt_bias(const float* __restrict__ A, const float* __restrict__ Bm,
              const float* __restrict__ bias1, const float* __restrict__ bias2,
              float* __restrict__ C, int M, int N, int K)
{
    __shared__ float As[16][128];
    __shared__ float Bs[16][64];

    const int tid = threadIdx.x;
    const int m0  = blockIdx.y * 128;
    const int n0  = blockIdx.x * 64;
    const int ty8 = (tid >> 4) * 8;
    const int tx4 = (tid & 15) * 4;

    unsigned long long acc2[4][4];
#pragma unroll
    for (int p = 0; p < 4; ++p)
#pragma unroll
        for (int j = 0; j < 4; ++j) acc2[p][j] = 0ULL;

    const int ntile = K >> 4;
    for (int kt = 0; kt < ntile; ++kt) {
        const int k0 = kt << 4;
#pragma unroll
        for (int r = 0; r < 2; ++r) {
            int idx = tid + (r << 8);
            int m = idx >> 2, kq = idx & 3;
            float4 v = *(const float4*)&A[(size_t)(m0 + m) * K + k0 + (kq << 2)];
            As[kq * 4 + 0][m] = v.x; As[kq * 4 + 1][m] = v.y;
            As[kq * 4 + 2][m] = v.z; As[kq * 4 + 3][m] = v.w;
        }
        {
            int n = tid >> 2, kq = tid & 3;
            float4 v = *(const float4*)&Bm[(size_t)(n0 + n) * K + k0 + (kq << 2)];
            Bs[kq * 4 + 0][n] = v.x; Bs[kq * 4 + 1][n] = v.y;
            Bs[kq * 4 + 2][n] = v.z; Bs[kq * 4 + 3][n] = v.w;
        }
        __syncthreads();

#pragma unroll
        for (int kk = 0; kk < 16; ++kk) {
            ulonglong2 a01 = *(const ulonglong2*)&As[kk][ty8];
            ulonglong2 a23 = *(const ulonglong2*)&As[kk][ty8 + 4];
            float4 bv = *(const float4*)&Bs[kk][tx4];
            unsigned long long am[4] = {a01.x, a01.y, a23.x, a23.y};
            float br[4] = {bv.x, bv.y, bv.z, bv.w};
#pragma unroll
            for (int j = 0; j < 4; ++j) {
                unsigned long long bp = pack2(br[j], br[j]);
#pragma unroll
                for (int p = 0; p < 4; ++p) fma2(acc2[p][j], am[p], bp);
            }
        }
        __syncthreads();
    }

    float bvv[4];
#pragma unroll
    for (int j = 0; j < 4; ++j) {
        float b = bias1[n0 + tx4 + j];
        if (bias2) b += bias2[n0 + tx4 + j];
        bvv[j] = b;
    }
#pragma unroll
    for (int p = 0; p < 4; ++p) {
        float4 o0, o1;
        float2 u0 = unpack2(acc2[p][0]);
        float2 u1 = unpack2(acc2[p][1]);
        float2 u2 = unpack2(acc2[p][2]);
        float2 u3 = unpack2(acc2[p][3]);
        o0.x = u0.x + bvv[0]; o0.y = u1.x + bvv[1]; o0.z = u2.x + bvv[2]; o0.w = u3.x + bvv[3];
        o1.x = u0.y + bvv[0]; o1.y = u1.y + bvv[1]; o1.z = u2.y + bvv[2]; o1.w = u3.y + bvv[3];
        *(float4*)&C[(size_t)(m0 + ty8 + 2 * p)     * N + n0 + tx4] = o0;
        *(float4*)&C[(size_t)(m0 + ty8 + 2 * p + 1) * N + n0 + tx4] = o1;
    }
}

// =====================================================================
// Recurrent LSTM scan v8: dual-stream pipeline (v7 logic) with the
// compile-proven v4 body shape (batch chunks of 4, acc[2][4]).
//   Cluster (8 CTAs) owns 16 batches = stream A (8) + stream B (8).
//   While one stream's h exchange (STG -> split cluster barrier -> peer
//   LDG) is in flight, the CTA computes the other stream's dot+gates.
//   Barrier pattern per iteration (at most one outstanding arrive):
//     halfA(t); wait(B t-1); stageB(t-1); arrive(A t);
//     halfB(t); wait(A t);   stageA(t);   arrive(B t);
//   Dot engine: R=4 rows/thread row-pair-packed W in regs (rW[2][32]),
//   kg = tid&7 interleaved k, broadcast LDS.32 h reads, FMA2, shfl_xor
//   reduce over kg. xp loads use .cs to keep h slices L2-resident.
// =====================================================================
#define PB 260   // hS pitch (floats)
#define PE 132   // ex pitch (floats)

#define CARR()  asm volatile("barrier.cluster.arrive.aligned;" ::: "memory")
#define CWAIT() asm volatile("barrier.cluster.wait.aligned;"   ::: "memory")

__device__ __forceinline__ float fsig(float x) {
    x = fminf(fmaxf(x, -30.f), 30.f);
    return __fdividef(1.f, 1.f + __expf(-x));
}
__device__ __forceinline__ float ftanh_(float x) {
    x = fminf(fmaxf(x, -15.f), 15.f);
    float e = __expf(-2.f * x);
    return __fdividef(1.f - e, 1.f + e);
}

// One stream's step: dot (8 batches, 2 chunks of 4) + reduce + gates + h store.
__device__ __forceinline__ void half_step(
    int t, int bbase, int rank, int tid, int kg, int r0,
    const unsigned long long (&rW)[2][32],
    const float* __restrict__ xpg, float* __restrict__ seq_out,
    const float* hSs, float* exs, float& cst)
{
    const int eb = tid >> 5, ec = tid & 31;

    // xp prefetch (independent of h; streaming hint)
    float xv[4];
#pragma unroll
    for (int g = 0; g < 4; ++g)
        xv[g] = ldg_cs(&xpg[((size_t)(bbase + eb) * T_ + t) * G_ +
                            (g << 8) + (rank << 5) + ec]);

    const float* hp = hSs + kg;
#pragma unroll
    for (int bc = 0; bc < 2; ++bc) {
        unsigned long long acc[2][4];
#pragma unroll
        for (int b = 0; b < 4; ++b) { acc[0][b] = 0ULL; acc[1][b] = 0ULL; }

#pragma unroll
        for (int jj = 0; jj < 32; ++jj) {
            const int ko = jj << 3;
#pragma unroll
            for (int b = 0; b < 4; ++b) {
                float hv = hp[((bc << 2) + b) * PB + ko];
                unsigned long long h2 = pack2(hv, hv);
                fma2(acc[0][b], rW[0][jj], h2);
                fma2(acc[1][b], rW[1][jj], h2);
            }
        }
        // reduce over 8 kg lanes (3 packed shuffle-add stages)
#pragma unroll
        for (int st = 1; st <= 4; st <<= 1) {
#pragma unroll
            for (int b = 0; b < 4; ++b) {
                acc[0][b] = add2(acc[0][b], shflx64(acc[0][b], st));
                acc[1][b] = add2(acc[1][b], shflx64(acc[1][b], st));
            }
        }
        if (kg == 0) {
#pragma unroll
            for (int b = 0; b < 4; ++b) {
                *(unsigned long long*)&exs[((bc << 2) + b) * PE + r0]     = acc[0][b];
                *(unsigned long long*)&exs[((bc << 2) + b) * PE + r0 + 2] = acc[1][b];
            }
        }
    }
    __syncthreads();

    // gates + state + h store (one (b,c) per thread)
    {
        float iv = exs[eb * PE + ec]      + xv[0];
        float fv = exs[eb * PE + 32 + ec] + xv[1];
        float gv = exs[eb * PE + 64 + ec] + xv[2];
        float ov = exs[eb * PE + 96 + ec] + xv[3];
        float ig = fsig(iv), fg = fsig(fv), gg = ftanh_(gv), og = fsig(ov);
        cst = fg * cst + ig * gg;
        seq_out[((size_t)(bbase + eb) * T_ + t) * H_ + (rank << 5) + ec] =
            og * ftanh_(cst);
    }
}

// Stage one stream's h(tt) from global into its SMEM buffer.
__device__ __forceinline__ void stage_h(
    int tt, int bbase, int tid,
    const float* __restrict__ seq_out, float* hSs)
{
#pragma unroll
    for (int j = 0; j < 2; ++j) {
        int f = tid + (j << 8);
        int b = f >> 6, q = f & 63;
        float4 v = *(const float4*)&seq_out[((size_t)(bbase + b) * T_ + tt) * H_ + (q << 2)];
        *(float4*)&hSs[b * PB + (q << 2)] = v;
    }
    __syncthreads();
}

__global__ void __cluster_dims__(8, 1, 1) __launch_bounds__(256, 1)
lstm_rec(const float* __restrict__ Whh, const float* __restrict__ xpg,
         float* __restrict__ seq_out)
{
    __shared__ float hSA[8 * PB];
    __shared__ float hSB[8 * PB];
    __shared__ float exA[8 * PE];
    __shared__ float exB[8 * PE];

    const int tid  = threadIdx.x;
    const int rank = blockIdx.x & 7;
    const int b0   = (blockIdx.x >> 3) * 16;   // stream A: b0..b0+7, B: +8..+15
    const int bA   = b0, bB = b0 + 8;

    const int kg = tid & 7;
    const int rg = tid >> 3;
    const int r0 = rg << 2;

    // W slice into registers: row-pairs packed, k = jj*8 + kg
    unsigned long long rW[2][32];
#pragma unroll
    for (int rp = 0; rp < 2; ++rp) {
        int rA = r0 + 2 * rp;
        int grA = ((rA >> 5) << 8) + (rank << 5) + (rA & 31);
#pragma unroll
        for (int jj = 0; jj < 32; ++jj) {
            int k = (jj << 3) + kg;
            rW[rp][jj] = pack2(__ldg(&Whh[(size_t)grA * H_ + k]),
                               __ldg(&Whh[(size_t)(grA + 1) * H_ + k]));
        }
    }

    // zero both h buffers (t=0 state)
    for (int idx = tid; idx < 8 * PB; idx += 256) { hSA[idx] = 0.f; hSB[idx] = 0.f; }

    float cstA = 0.f, cstB = 0.f;
    __syncthreads();

    // ---- priming (t = 0): both streams start from h = 0 ----
    half_step(0, bA, rank, tid, kg, r0, rW, xpg, seq_out, hSA, exA, cstA);
    CARR();                                   // post A(0) exchange
    half_step(0, bB, rank, tid, kg, r0, rW, xpg, seq_out, hSB, exB, cstB);
    CWAIT();                                  // all peers' hA(0) visible
    stage_h(0, bA, tid, seq_out, hSA);
    CARR();                                   // post B(0) exchange

    // ---- steady-state pipeline ----
    for (int t = 1; t < T_; ++t) {
        half_step(t, bA, rank, tid, kg, r0, rW, xpg, seq_out, hSA, exA, cstA);
        CWAIT();                              // hB(t-1) visible (hidden by halfA)
        stage_h(t - 1, bB, tid, seq_out, hSB);
        CARR();                               // post A(t) exchange
        half_step(t, bB, rank, tid, kg, r0, rW, xpg, seq_out, hSB, exB, cstB);
        CWAIT();                              // hA(t) visible (hidden by halfB)
        stage_h(t, bA, tid, seq_out, hSA);
        CARR();                               // post B(t) exchange
    }
    CWAIT();                                  // balance final arrive
}

// =====================================================================
// Launcher
// =====================================================================
extern "C" void kernel_launch(void* const* d_in, const int* in_sizes, int n_in,
                              void* d_out, int out_size)
{
    const float* x     = (const float*)d_in[0];
    const float* eWih0 = (const float*)d_in[1];
    const float* eWhh0 = (const float*)d_in[2];
    const float* ebih0 = (const float*)d_in[3];
    const float* ebhh0 = (const float*)d_in[4];
    const float* eWih1 = (const float*)d_in[5];
    const float* eWhh1 = (const float*)d_in[6];
    const float* ebih1 = (const float*)d_in[7];
    const float* ebhh1 = (const float*)d_in[8];
    const float* dWih0 = (const float*)d_in[9];
    const float* dWhh0 = (const float*)d_in[10];
    const float* dbih0 = (const float*)d_in[11];
    const float* dbhh0 = (const float*)d_in[12];
    const float* dWih1 = (const float*)d_in[13];
    const float* dWhh1 = (const float*)d_in[14];
    const float* dbih1 = (const float*)d_in[15];
    const float* dbhh1 = (const float*)d_in[16];
    const float* out_W = (const float*)d_in[17];
    const float* out_b = (const float*)d_in[18];
    float* out = (float*)d_out;

    void* p;
    cudaGetSymbolAddress(&p, g_xp); float* xp = (float*)p;
    cudaGetSymbolAddress(&p, g_s0); float* s0 = (float*)p;
    cudaGetSymbolAddress(&p, g_s1); float* s1 = (float*)p;

    dim3 blk(256);
    dim3 gXP(G_ / 64, BT_ / 128);   // N=1024 tiles x M tiles
    dim3 gPR(I_ / 64, BT_ / 128);   // projection N=64

    // encoder layer 0 (K = I = 64)
    gemm_abt_bias<<<gXP, blk>>>(x, eWih0, ebih0, ebhh0, xp, BT_, G_, I_);
    lstm_rec<<<128, blk>>>(eWhh0, xp, s0);
    // encoder layer 1 (K = H)
    gemm_abt_bias<<<gXP, blk>>>(s0, eWih1, ebih1, ebhh1, xp, BT_, G_, H_);
    lstm_rec<<<128, blk>>>(eWhh1, xp, s1);
    // decoder layer 0
    gemm_abt_bias<<<gXP, blk>>>(s1, dWih0, dbih0, dbhh0, xp, BT_, G_, H_);
    lstm_rec<<<128, blk>>>(dWhh0, xp, s0);
    // decoder layer 1
    gemm_abt_bias<<<gXP, blk>>>(s0, dWih1, dbih1, dbhh1, xp, BT_, G_, H_);
    lstm_rec<<<128, blk>>>(dWhh1, xp, s1);
    // output projection (N = I = 64, K = H)
    gemm_abt_bias<<<gPR, blk>>>(s1, out_W, out_b, nullptr, out, BT_, I_, H_);
}

// round 12
// speedup vs baseline: 1.2169x; 1.1545x over previous
#include <cuda_runtime.h>
#include <cstdint>
#include <cstddef>

// Problem constants
#define B_  256
#define T_  512
#define I_  64
#define H_  256
#define G_  1024            // 4*H
#define BT_ (B_ * T_)       // 131072

// -------- scratch (device globals; no allocation allowed) --------
__device__ float g_xp[(size_t)BT_ * G_];   // gate pre-activations for current layer
__device__ float g_s0[(size_t)BT_ * H_];   // layer output sequence (ping)
__device__ float g_s1[(size_t)BT_ * H_];   // layer output sequence (pong)

// ---------------- packed f32x2 helpers (PTX-only path) ----------------
__device__ __forceinline__ unsigned long long pack2(float lo, float hi) {
    unsigned long long r;
    asm("mov.b64 %0, {%1, %2};" : "=l"(r)
        : "r"(__float_as_uint(lo)), "r"(__float_as_uint(hi)));
    return r;
}
__device__ __forceinline__ void fma2(unsigned long long& d,
                                     unsigned long long a, unsigned long long b) {
    asm("fma.rn.f32x2 %0, %1, %2, %0;" : "+l"(d) : "l"(a), "l"(b));
}
__device__ __forceinline__ float2 unpack2(unsigned long long v) {
    unsigned lo, hi;
    asm("mov.b64 {%0, %1}, %2;" : "=r"(lo), "=r"(hi) : "l"(v));
    return make_float2(__uint_as_float(lo), __uint_as_float(hi));
}
__device__ __forceinline__ unsigned long long add2(unsigned long long a,
                                                   unsigned long long b) {
    unsigned long long r;
    asm("add.rn.f32x2 %0, %1, %2;" : "=l"(r) : "l"(a), "l"(b));
    return r;
}
__device__ __forceinline__ unsigned long long shflx64(unsigned long long v, int m) {
    unsigned lo, hi;
    asm("mov.b64 {%0, %1}, %2;" : "=r"(lo), "=r"(hi) : "l"(v));
    lo = __shfl_xor_sync(0xffffffffu, lo, m);
    hi = __shfl_xor_sync(0xffffffffu, hi, m);
    unsigned long long r;
    asm("mov.b64 %0, {%1, %2};" : "=l"(r) : "r"(lo), "r"(hi));
    return r;
}

// =====================================================================
// GEMM v2: C[M,N] = A[M,K] * B[N,K]^T + bias1[N] (+ bias2[N])
// BM=128, BN=64, BK=16, 256 threads, f32x2 over M-pairs.
// NEW: 2-stage SMEM double-buffer + register prefetch (LDG of kt+1
// issued before compute of kt -> DRAM latency hidden by ~1-2k cyc of
// FMA2), occupancy 3 CTAs/SM, padded SMEM (As pitch 132, Bs 68 ->
// 2-way STS conflicts instead of 4-way; both pitches keep 16B align).
// =====================================================================
#define APITCH 132
#define BPITCH 68

__global__ void __launch_bounds__(256, 3)
gemm_abt_bias(const float* __restrict__ A, const float* __restrict__ Bm,
              const float* __restrict__ bias1, const float* __restrict__ bias2,
              float* __restrict__ C, int M, int N, int K)
{
    __shared__ float As[2][16 * APITCH];
    __shared__ float Bs[2][16 * BPITCH];

    const int tid = threadIdx.x;
    const int m0  = blockIdx.y * 128;
    const int n0  = blockIdx.x * 64;
    const int ty8 = (tid >> 4) * 8;
    const int tx4 = (tid & 15) * 4;

    const int lm = tid >> 2;        // A/B row handled by this thread
    const int lk = (tid & 3) << 2;  // k-quad within tile

    const float* pA0 = &A[(size_t)(m0 + lm) * K + lk];
    const float* pA1 = &A[(size_t)(m0 + 64 + lm) * K + lk];
    const float* pB  = &Bm[(size_t)(n0 + lm) * K + lk];

    unsigned long long acc2[4][4];
#pragma unroll
    for (int p = 0; p < 4; ++p)
#pragma unroll
        for (int j = 0; j < 4; ++j) acc2[p][j] = 0ULL;

    const int ntile = K >> 4;

    // prologue: load tile 0 into regs, store to buffer 0
    float4 ra0 = *(const float4*)pA0;
    float4 ra1 = *(const float4*)pA1;
    float4 rb  = *(const float4*)pB;
    {
        float* as = As[0];
        float* bs = Bs[0];
        as[(lk + 0) * APITCH + lm]      = ra0.x;
        as[(lk + 1) * APITCH + lm]      = ra0.y;
        as[(lk + 2) * APITCH + lm]      = ra0.z;
        as[(lk + 3) * APITCH + lm]      = ra0.w;
        as[(lk + 0) * APITCH + 64 + lm] = ra1.x;
        as[(lk + 1) * APITCH + 64 + lm] = ra1.y;
        as[(lk + 2) * APITCH + 64 + lm] = ra1.z;
        as[(lk + 3) * APITCH + 64 + lm] = ra1.w;
        bs[(lk + 0) * BPITCH + lm] = rb.x;
        bs[(lk + 1) * BPITCH + lm] = rb.y;
        bs[(lk + 2) * BPITCH + lm] = rb.z;
        bs[(lk + 3) * BPITCH + lm] = rb.w;
    }
    __syncthreads();

    for (int kt = 0; kt < ntile; ++kt) {
        // prefetch tile kt+1 into registers (latency hidden by compute)
        const bool more = (kt + 1) < ntile;
        if (more) {
            int off = (kt + 1) << 4;
            ra0 = *(const float4*)(pA0 + off);
            ra1 = *(const float4*)(pA1 + off);
            rb  = *(const float4*)(pB  + off);
        }

        // compute from current buffer
        const float* as = As[kt & 1];
        const float* bs = Bs[kt & 1];
#pragma unroll
        for (int kk = 0; kk < 16; ++kk) {
            ulonglong2 a01 = *(const ulonglong2*)&as[kk * APITCH + ty8];
            ulonglong2 a23 = *(const ulonglong2*)&as[kk * APITCH + ty8 + 4];
            float4 bv = *(const float4*)&bs[kk * BPITCH + tx4];
            unsigned long long am[4] = {a01.x, a01.y, a23.x, a23.y};
            float br[4] = {bv.x, bv.y, bv.z, bv.w};
#pragma unroll
            for (int j = 0; j < 4; ++j) {
                unsigned long long bp = pack2(br[j], br[j]);
#pragma unroll
                for (int p = 0; p < 4; ++p) fma2(acc2[p][j], am[p], bp);
            }
        }

        // store prefetched tile into the other buffer
        if (more) {
            float* asn = As[(kt + 1) & 1];
            float* bsn = Bs[(kt + 1) & 1];
            asn[(lk + 0) * APITCH + lm]      = ra0.x;
            asn[(lk + 1) * APITCH + lm]      = ra0.y;
            asn[(lk + 2) * APITCH + lm]      = ra0.z;
            asn[(lk + 3) * APITCH + lm]      = ra0.w;
            asn[(lk + 0) * APITCH + 64 + lm] = ra1.x;
            asn[(lk + 1) * APITCH + 64 + lm] = ra1.y;
            asn[(lk + 2) * APITCH + 64 + lm] = ra1.z;
            asn[(lk + 3) * APITCH + 64 + lm] = ra1.w;
            bsn[(lk + 0) * BPITCH + lm] = rb.x;
            bsn[(lk + 1) * BPITCH + lm] = rb.y;
            bsn[(lk + 2) * BPITCH + lm] = rb.z;
            bsn[(lk + 3) * BPITCH + lm] = rb.w;
            __syncthreads();
        }
    }

    float bvv[4];
#pragma unroll
    for (int j = 0; j < 4; ++j) {
        float b = bias1[n0 + tx4 + j];
        if (bias2) b += bias2[n0 + tx4 + j];
        bvv[j] = b;
    }
#pragma unroll
    for (int p = 0; p < 4; ++p) {
        float4 o0, o1;
        float2 u0 = unpack2(acc2[p][0]);
        float2 u1 = unpack2(acc2[p][1]);
        float2 u2 = unpack2(acc2[p][2]);
        float2 u3 = unpack2(acc2[p][3]);
        o0.x = u0.x + bvv[0]; o0.y = u1.x + bvv[1]; o0.z = u2.x + bvv[2]; o0.w = u3.x + bvv[3];
        o1.x = u0.y + bvv[0]; o1.y = u1.y + bvv[1]; o1.z = u2.y + bvv[2]; o1.w = u3.y + bvv[3];
        *(float4*)&C[(size_t)(m0 + ty8 + 2 * p)     * N + n0 + tx4] = o0;
        *(float4*)&C[(size_t)(m0 + ty8 + 2 * p + 1) * N + n0 + tx4] = o1;
    }
}

// =====================================================================
// Recurrent LSTM scan: byte-identical to the R6-passing v4.
// (kept fixed this round for clean GEMM-vs-rec time attribution)
// =====================================================================
#define PB 260   // hS pitch (floats)
#define PE 132   // ex pitch (floats)

__device__ __forceinline__ float fsig(float x) {
    x = fminf(fmaxf(x, -30.f), 30.f);
    return __fdividef(1.f, 1.f + __expf(-x));
}
__device__ __forceinline__ float ftanh_(float x) {
    x = fminf(fmaxf(x, -15.f), 15.f);
    float e = __expf(-2.f * x);
    return __fdividef(1.f - e, 1.f + e);
}

__global__ void __cluster_dims__(8, 1, 1) __launch_bounds__(256, 1)
lstm_rec(const float* __restrict__ Whh, const float* __restrict__ xpg,
         float* __restrict__ seq_out)
{
    __shared__ float hS[16 * PB];    // h_{t-1}: [batch][k]
    __shared__ float ex[16 * PE];    // dots: [batch][CTA-local row]

    const int tid  = threadIdx.x;
    const int rank = blockIdx.x & 7;
    const int b0   = (blockIdx.x >> 3) * 16;

    const int kg = tid & 7;          // k-interleave group
    const int rg = tid >> 3;         // rowgroup 0..31
    const int r0 = rg << 2;          // first of 4 CTA-local rows

    // W slice into registers: row-pairs packed, k = jj*8 + kg
    unsigned long long rW[2][32];
#pragma unroll
    for (int rp = 0; rp < 2; ++rp) {
        int rA = r0 + 2 * rp;
        int grA = ((rA >> 5) << 8) + (rank << 5) + (rA & 31);
#pragma unroll
        for (int jj = 0; jj < 32; ++jj) {
            int k = (jj << 3) + kg;
            rW[rp][jj] = pack2(__ldg(&Whh[(size_t)grA * H_ + k]),
                               __ldg(&Whh[(size_t)(grA + 1) * H_ + k]));
        }
    }

    // zero h buffer (t=0 state)
    for (int idx = tid; idx < 16 * PB; idx += 256) hS[idx] = 0.f;

    // epilogue mapping (t-invariant): idx = b*32 + c
    int gb[2], gc[2];
#pragma unroll
    for (int u = 0; u < 2; ++u) {
        int idx = tid + (u << 8);
        gb[u] = idx >> 5; gc[u] = idx & 31;
    }
    float cst[2] = {0.f, 0.f};

    __syncthreads();

    for (int t = 0; t < T_; ++t) {
        // ---- stage h_{t-1}: coalesced LDG.128 -> conflict-free STS.128 ----
        if (t > 0) {
#pragma unroll
            for (int jj2 = 0; jj2 < 4; ++jj2) {
                int f = tid + (jj2 << 8);
                int b = f >> 6, k0 = (f & 63) << 2;
                float4 v = *(const float4*)&seq_out[((size_t)(b0 + b) * T_ + (t - 1)) * H_ + k0];
                *(float4*)&hS[b * PB + k0] = v;
            }
        }
        // prefetch xp for this step (independent of h)
        float xv[2][4];
#pragma unroll
        for (int u = 0; u < 2; ++u)
#pragma unroll
            for (int g = 0; g < 4; ++g)
                xv[u][g] = __ldg(&xpg[((size_t)(b0 + gb[u]) * T_ + t) * G_ +
                                      (g << 8) + (rank << 5) + gc[u]]);
        __syncthreads();

        // ---- dot in 4 batch-chunks of 4 (bounds live registers) ----
        const float* hp = hS + kg;
#pragma unroll
        for (int bc = 0; bc < 4; ++bc) {
            unsigned long long acc[2][4];
#pragma unroll
            for (int b = 0; b < 4; ++b) { acc[0][b] = 0ULL; acc[1][b] = 0ULL; }

#pragma unroll
            for (int jj = 0; jj < 32; ++jj) {
                const int ko = jj << 3;
#pragma unroll
                for (int b = 0; b < 4; ++b) {
                    float hv = hp[((bc << 2) + b) * PB + ko];
                    unsigned long long h2 = pack2(hv, hv);
                    fma2(acc[0][b], rW[0][jj], h2);
                    fma2(acc[1][b], rW[1][jj], h2);
                }
            }

            // reduce over 8 kg groups: 3 packed shuffle-add stages
#pragma unroll
            for (int st = 1; st <= 4; st <<= 1) {
#pragma unroll
                for (int b = 0; b < 4; ++b) {
                    acc[0][b] = add2(acc[0][b], shflx64(acc[0][b], st));
                    acc[1][b] = add2(acc[1][b], shflx64(acc[1][b], st));
                }
            }
            if (kg == 0) {
#pragma unroll
                for (int b = 0; b < 4; ++b) {
                    *(unsigned long long*)&ex[((bc << 2) + b) * PE + r0]     = acc[0][b];
                    *(unsigned long long*)&ex[((bc << 2) + b) * PE + r0 + 2] = acc[1][b];
                }
            }
        }
        __syncthreads();

        // ---- gates + state update + h write ----
#pragma unroll
        for (int u = 0; u < 2; ++u) {
            int b = gb[u], c = gc[u];
            float iv = ex[b * PE + c]      + xv[u][0];
            float fv = ex[b * PE + 32 + c] + xv[u][1];
            float gv = ex[b * PE + 64 + c] + xv[u][2];
            float ov = ex[b * PE + 96 + c] + xv[u][3];
            float ig = fsig(iv), fg = fsig(fv), gg = ftanh_(gv), og = fsig(ov);
            cst[u] = fg * cst[u] + ig * gg;
            seq_out[((size_t)(b0 + b) * T_ + t) * H_ + (rank << 5) + c] = og * ftanh_(cst[u]);
        }

        // ---- cluster barrier: release h writes / acquire peers' ----
        asm volatile("barrier.cluster.arrive.aligned;\n\t"
                     "barrier.cluster.wait.aligned;\n\t" ::: "memory");
    }
}

// =====================================================================
// Launcher
// =====================================================================
extern "C" void kernel_launch(void* const* d_in, const int* in_sizes, int n_in,
                              void* d_out, int out_size)
{
    const float* x     = (const float*)d_in[0];
    const float* eWih0 = (const float*)d_in[1];
    const float* eWhh0 = (const float*)d_in[2];
    const float* ebih0 = (const float*)d_in[3];
    const float* ebhh0 = (const float*)d_in[4];
    const float* eWih1 = (const float*)d_in[5];
    const float* eWhh1 = (const float*)d_in[6];
    const float* ebih1 = (const float*)d_in[7];
    const float* ebhh1 = (const float*)d_in[8];
    const float* dWih0 = (const float*)d_in[9];
    const float* dWhh0 = (const float*)d_in[10];
    const float* dbih0 = (const float*)d_in[11];
    const float* dbhh0 = (const float*)d_in[12];
    const float* dWih1 = (const float*)d_in[13];
    const float* dWhh1 = (const float*)d_in[14];
    const float* dbih1 = (const float*)d_in[15];
    const float* dbhh1 = (const float*)d_in[16];
    const float* out_W = (const float*)d_in[17];
    const float* out_b = (const float*)d_in[18];
    float* out = (float*)d_out;

    void* p;
    cudaGetSymbolAddress(&p, g_xp); float* xp = (float*)p;
    cudaGetSymbolAddress(&p, g_s0); float* s0 = (float*)p;
    cudaGetSymbolAddress(&p, g_s1); float* s1 = (float*)p;

    dim3 blk(256);
    dim3 gXP(G_ / 64, BT_ / 128);   // N=1024 tiles x M tiles
    dim3 gPR(I_ / 64, BT_ / 128);   // projection N=64

    // encoder layer 0 (K = I = 64)
    gemm_abt_bias<<<gXP, blk>>>(x, eWih0, ebih0, ebhh0, xp, BT_, G_, I_);
    lstm_rec<<<128, blk>>>(eWhh0, xp, s0);
    // encoder layer 1 (K = H)
    gemm_abt_bias<<<gXP, blk>>>(s0, eWih1, ebih1, ebhh1, xp, BT_, G_, H_);
    lstm_rec<<<128, blk>>>(eWhh1, xp, s1);
    // decoder layer 0
    gemm_abt_bias<<<gXP, blk>>>(s1, dWih0, dbih0, dbhh0, xp, BT_, G_, H_);
    lstm_rec<<<128, blk>>>(dWhh0, xp, s0);
    // decoder layer 1
    gemm_abt_bias<<<gXP, blk>>>(s0, dWih1, dbih1, dbhh1, xp, BT_, G_, H_);
    lstm_rec<<<128, blk>>>(dWhh1, xp, s1);
    // output projection (N = I = 64, K = H)
    gemm_abt_bias<<<gPR, blk>>>(s1, out_W, out_b, nullptr, out, BT_, I_, H_);
}

// round 15
// speedup vs baseline: 1.7049x; 1.4010x over previous
#include <cuda_runtime.h>
#include <cuda_bf16.h>
#include <cstdint>
#include <cstddef>

// Problem constants
#define B_  256
#define T_  512
#define I_  64
#define H_  256
#define G_  1024            // 4*H
#define BT_ (B_ * T_)       // 131072

// -------- scratch (device globals; no allocation allowed) --------
__device__ float g_xp[(size_t)BT_ * G_];   // gate pre-activations for current layer
__device__ float g_s0[(size_t)BT_ * H_];   // layer output sequence (ping)
__device__ float g_s1[(size_t)BT_ * H_];   // layer output sequence (pong)

// ---------------- packed f32x2 helpers (GEMM kernel) ----------------
__device__ __forceinline__ unsigned long long pack2(float lo, float hi) {
    unsigned long long r;
    asm("mov.b64 %0, {%1, %2};" : "=l"(r)
        : "r"(__float_as_uint(lo)), "r"(__float_as_uint(hi)));
    return r;
}
__device__ __forceinline__ void fma2(unsigned long long& d,
                                     unsigned long long a, unsigned long long b) {
    asm("fma.rn.f32x2 %0, %1, %2, %0;" : "+l"(d) : "l"(a), "l"(b));
}
__device__ __forceinline__ float2 unpack2(unsigned long long v) {
    unsigned lo, hi;
    asm("mov.b64 {%0, %1}, %2;" : "=r"(lo), "=r"(hi) : "l"(v));
    return make_float2(__uint_as_float(lo), __uint_as_float(hi));
}

// =====================================================================
// GEMM v2 (R12-passing): double-buffered, register-prefetch, occ 3.
// =====================================================================
#define APITCH 132
#define BPITCH 68

__global__ void __launch_bounds__(256, 3)
gemm_abt_bias(const float* __restrict__ A, const float* __restrict__ Bm,
              const float* __restrict__ bias1, const float* __restrict__ bias2,
              float* __restrict__ C, int M, int N, int K)
{
    __shared__ float As[2][16 * APITCH];
    __shared__ float Bs[2][16 * BPITCH];

    const int tid = threadIdx.x;
    const int m0  = blockIdx.y * 128;
    const int n0  = blockIdx.x * 64;
    const int ty8 = (tid >> 4) * 8;
    const int tx4 = (tid & 15) * 4;

    const int lm = tid >> 2;
    const int lk = (tid & 3) << 2;

    const float* pA0 = &A[(size_t)(m0 + lm) * K + lk];
    const float* pA1 = &A[(size_t)(m0 + 64 + lm) * K + lk];
    const float* pB  = &Bm[(size_t)(n0 + lm) * K + lk];

    unsigned long long acc2[4][4];
#pragma unroll
    for (int p = 0; p < 4; ++p)
#pragma unroll
        for (int j = 0; j < 4; ++j) acc2[p][j] = 0ULL;

    const int ntile = K >> 4;

    float4 ra0 = *(const float4*)pA0;
    float4 ra1 = *(const float4*)pA1;
    float4 rb  = *(const float4*)pB;
    {
        float* as = As[0];
        float* bs = Bs[0];
        as[(lk + 0) * APITCH + lm]      = ra0.x;
        as[(lk + 1) * APITCH + lm]      = ra0.y;
        as[(lk + 2) * APITCH + lm]      = ra0.z;
        as[(lk + 3) * APITCH + lm]      = ra0.w;
        as[(lk + 0) * APITCH + 64 + lm] = ra1.x;
        as[(lk + 1) * APITCH + 64 + lm] = ra1.y;
        as[(lk + 2) * APITCH + 64 + lm] = ra1.z;
        as[(lk + 3) * APITCH + 64 + lm] = ra1.w;
        bs[(lk + 0) * BPITCH + lm] = rb.x;
        bs[(lk + 1) * BPITCH + lm] = rb.y;
        bs[(lk + 2) * BPITCH + lm] = rb.z;
        bs[(lk + 3) * BPITCH + lm] = rb.w;
    }
    __syncthreads();

    for (int kt = 0; kt < ntile; ++kt) {
        const bool more = (kt + 1) < ntile;
        if (more) {
            int off = (kt + 1) << 4;
            ra0 = *(const float4*)(pA0 + off);
            ra1 = *(const float4*)(pA1 + off);
            rb  = *(const float4*)(pB  + off);
        }

        const float* as = As[kt & 1];
        const float* bs = Bs[kt & 1];
#pragma unroll
        for (int kk = 0; kk < 16; ++kk) {
            ulonglong2 a01 = *(const ulonglong2*)&as[kk * APITCH + ty8];
            ulonglong2 a23 = *(const ulonglong2*)&as[kk * APITCH + ty8 + 4];
            float4 bv = *(const float4*)&bs[kk * BPITCH + tx4];
            unsigned long long am[4] = {a01.x, a01.y, a23.x, a23.y};
            float br[4] = {bv.x, bv.y, bv.z, bv.w};
#pragma unroll
            for (int j = 0; j < 4; ++j) {
                unsigned long long bp = pack2(br[j], br[j]);
#pragma unroll
                for (int p = 0; p < 4; ++p) fma2(acc2[p][j], am[p], bp);
            }
        }

        if (more) {
            float* asn = As[(kt + 1) & 1];
            float* bsn = Bs[(kt + 1) & 1];
            asn[(lk + 0) * APITCH + lm]      = ra0.x;
            asn[(lk + 1) * APITCH + lm]      = ra0.y;
            asn[(lk + 2) * APITCH + lm]      = ra0.z;
            asn[(lk + 3) * APITCH + lm]      = ra0.w;
            asn[(lk + 0) * APITCH + 64 + lm] = ra1.x;
            asn[(lk + 1) * APITCH + 64 + lm] = ra1.y;
            asn[(lk + 2) * APITCH + 64 + lm] = ra1.z;
            asn[(lk + 3) * APITCH + 64 + lm] = ra1.w;
            bsn[(lk + 0) * BPITCH + lm] = rb.x;
            bsn[(lk + 1) * BPITCH + lm] = rb.y;
            bsn[(lk + 2) * BPITCH + lm] = rb.z;
            bsn[(lk + 3) * BPITCH + lm] = rb.w;
            __syncthreads();
        }
    }

    float bvv[4];
#pragma unroll
    for (int j = 0; j < 4; ++j) {
        float b = bias1[n0 + tx4 + j];
        if (bias2) b += bias2[n0 + tx4 + j];
        bvv[j] = b;
    }
#pragma unroll
    for (int p = 0; p < 4; ++p) {
        float4 o0, o1;
        float2 u0 = unpack2(acc2[p][0]);
        float2 u1 = unpack2(acc2[p][1]);
        float2 u2 = unpack2(acc2[p][2]);
        float2 u3 = unpack2(acc2[p][3]);
        o0.x = u0.x + bvv[0]; o0.y = u1.x + bvv[1]; o0.z = u2.x + bvv[2]; o0.w = u3.x + bvv[3];
        o1.x = u0.y + bvv[0]; o1.y = u1.y + bvv[1]; o1.z = u2.y + bvv[2]; o1.w = u3.y + bvv[3];
        *(float4*)&C[(size_t)(m0 + ty8 + 2 * p)     * N + n0 + tx4] = o0;
        *(float4*)&C[(size_t)(m0 + ty8 + 2 * p + 1) * N + n0 + tx4] = o1;
    }
}

// =====================================================================
// Recurrent LSTM scan v9: warp-level HMMA (mma.sync m16n8k16 bf16) with
// fp32 hi/lo split. Per CTA/step: D[128,16] = Whi*hhi + Whi*hlo + Wlo*hhi
// accumulated fp32 in c-frags.
//   grid = 128 CTAs = 16 clusters x 8; cluster owns 16 batches.
//   Warp w owns gate rows [w*16, w*16+16). W frag arrays (bf16 hi/lo,
//   canonical m16n8k16 .row layout) built ONCE in SMEM; h staged per
//   step into frag-order B arrays (col layout). 16 k-tiles x 6 MMAs.
//   D -> ex via c-frag STS (conflict-free), then v4 gate epilogue,
//   coalesced h store, cluster barrier h-exchange (proven pattern).
// Fragment mappings (PTX m16n8k16, row.col):
//   A reg r: row = gid + (r&1)*8, k = ctib*2 + (r>>1)*8 (+kt*16); bf16x2 = (k, k+1)
//   B reg r: k = ctib*2 + r*8 (+kt*16), n = gid; bf16x2 = (k, k+1)
//   C reg r: row = gid + (r>>1)*8, n = ctib*2 + (r&1)
// =====================================================================
#define PE 132
// SMEM byte offsets
#define AFH_OFF  0
#define AFL_OFF  65536
#define BFH_OFF  131072
#define BFL_OFF  139264
#define EX_OFF   147456
#define REC_SMEM (EX_OFF + 16 * PE * 4)   // 155904 B

__device__ __forceinline__ uint32_t bfpack(float a, float b) {
    __nv_bfloat162 t = __floats2bfloat162_rn(a, b);   // x=a (low), y=b (high)
    return *reinterpret_cast<uint32_t*>(&t);
}
__device__ __forceinline__ void mma_bf16(float& c0, float& c1, float& c2, float& c3,
                                         uint32_t a0, uint32_t a1, uint32_t a2, uint32_t a3,
                                         uint32_t b0, uint32_t b1) {
    asm volatile(
        "mma.sync.aligned.m16n8k16.row.col.f32.bf16.bf16.f32 "
        "{%0,%1,%2,%3}, {%4,%5,%6,%7}, {%8,%9}, {%0,%1,%2,%3};"
        : "+f"(c0), "+f"(c1), "+f"(c2), "+f"(c3)
        : "r"(a0), "r"(a1), "r"(a2), "r"(a3), "r"(b0), "r"(b1));
}
__device__ __forceinline__ float fsig(float x) {
    x = fminf(fmaxf(x, -30.f), 30.f);
    return __fdividef(1.f, 1.f + __expf(-x));
}
__device__ __forceinline__ float ftanh_(float x) {
    x = fminf(fmaxf(x, -15.f), 15.f);
    float e = __expf(-2.f * x);
    return __fdividef(1.f - e, 1.f + e);
}

__global__ void __cluster_dims__(8, 1, 1) __launch_bounds__(256, 1)
lstm_rec(const float* __restrict__ Whh, const float* __restrict__ xpg,
         float* __restrict__ seq_out)
{
    extern __shared__ __align__(16) char smem[];
    uint32_t* AFH = (uint32_t*)(smem + AFH_OFF);   // [8w][16kt][32lane][4reg]
    uint32_t* AFL = (uint32_t*)(smem + AFL_OFF);
    uint32_t* BFH = (uint32_t*)(smem + BFH_OFF);   // [16kt][2nt][32lane][2reg]
    uint32_t* BFL = (uint32_t*)(smem + BFL_OFF);
    float*    ex  = (float*)(smem + EX_OFF);       // [16 b][PE rows]

    const int tid  = threadIdx.x;
    const int w    = tid >> 5;
    const int lane = tid & 31;
    const int gid  = lane >> 2;
    const int ctib = lane & 3;
    const int rank = blockIdx.x & 7;
    const int b0   = (blockIdx.x >> 3) * 16;

    // ---- build W fragment arrays once (hi/lo bf16 split) ----
    for (int i = tid; i < 16384; i += 256) {
        int reg = i & 3, ln = (i >> 2) & 31, kt = (i >> 7) & 15, ww = i >> 11;
        int g = ln >> 2, cb = ln & 3;
        int m  = ww * 16 + g + ((reg & 1) << 3);
        int k0 = kt * 16 + cb * 2 + ((reg >> 1) << 3);
        int gr = ((m >> 5) << 8) + (rank << 5) + (m & 31);
        float w0 = __ldg(&Whh[(size_t)gr * H_ + k0]);
        float w1 = __ldg(&Whh[(size_t)gr * H_ + k0 + 1]);
        __nv_bfloat16 h0 = __float2bfloat16(w0);
        __nv_bfloat16 h1 = __float2bfloat16(w1);
        AFH[i] = bfpack(__bfloat162float(h0), __bfloat162float(h1));
        AFL[i] = bfpack(w0 - __bfloat162float(h0), w1 - __bfloat162float(h1));
    }
    // zero B frags (t=0: h = 0)
    for (int i = tid; i < 2048; i += 256) { BFH[i] = 0u; BFL[i] = 0u; }

    // staging mapping: thread -> (batch, 16-k segment)
    const int sb = tid >> 4, skseg = (tid & 15) << 4;
    const int sgid = sb & 7, snt = sb >> 3, skt = skseg >> 4;

    // gate-epilogue mapping (v4): idx = b*32 + c
    int gb[2], gc[2];
#pragma unroll
    for (int u = 0; u < 2; ++u) {
        int idx = tid + (u << 8);
        gb[u] = idx >> 5; gc[u] = idx & 31;
    }
    float cst[2] = {0.f, 0.f};

    __syncthreads();

    for (int t = 0; t < T_; ++t) {
        // ---- stage h_{t-1} into frag-order bf16 hi/lo B arrays ----
        if (t > 0) {
            const float* src = &seq_out[((size_t)(b0 + sb) * T_ + (t - 1)) * H_ + skseg];
#pragma unroll
            for (int q = 0; q < 4; ++q) {
                float4 v = *(const float4*)&src[q << 2];
                float f[4] = {v.x, v.y, v.z, v.w};
#pragma unroll
                for (int e = 0; e < 2; ++e) {
                    int j = (q << 1) + e;            // k-pair index 0..7
                    float f0 = f[e * 2], f1 = f[e * 2 + 1];
                    int ln  = (sgid << 2) + (j & 3);
                    int reg = j >> 2;
                    int idx = (((skt << 1) + snt) << 6) + (ln << 1) + reg;
                    __nv_bfloat16 h0 = __float2bfloat16(f0);
                    __nv_bfloat16 h1 = __float2bfloat16(f1);
                    BFH[idx] = bfpack(__bfloat162float(h0), __bfloat162float(h1));
                    BFL[idx] = bfpack(f0 - __bfloat162float(h0), f1 - __bfloat162float(h1));
                }
            }
        }
        // prefetch xp (independent of h)
        float xv[2][4];
#pragma unroll
        for (int u = 0; u < 2; ++u)
#pragma unroll
            for (int g = 0; g < 4; ++g)
                xv[u][g] = __ldg(&xpg[((size_t)(b0 + gb[u]) * T_ + t) * G_ +
                                      (g << 8) + (rank << 5) + gc[u]]);
        __syncthreads();

        // ---- MMA: 16 k-tiles x (hi*hi + hi*lo + lo*hi), fp32 acc ----
        float c0[4] = {0.f, 0.f, 0.f, 0.f};   // nt = 0
        float c1[4] = {0.f, 0.f, 0.f, 0.f};   // nt = 1
#pragma unroll
        for (int kt = 0; kt < 16; ++kt) {
            uint4 Ah = ((const uint4*)AFH)[(w << 4 | kt) * 32 + lane];
            uint4 Al = ((const uint4*)AFL)[(w << 4 | kt) * 32 + lane];
            uint2 Bh0 = ((const uint2*)BFH)[((kt << 1) | 0) * 32 + lane];
            uint2 Bh1 = ((const uint2*)BFH)[((kt << 1) | 1) * 32 + lane];
            uint2 Bl0 = ((const uint2*)BFL)[((kt << 1) | 0) * 32 + lane];
            uint2 Bl1 = ((const uint2*)BFL)[((kt << 1) | 1) * 32 + lane];
            mma_bf16(c0[0], c0[1], c0[2], c0[3], Ah.x, Ah.y, Ah.z, Ah.w, Bh0.x, Bh0.y);
            mma_bf16(c1[0], c1[1], c1[2], c1[3], Ah.x, Ah.y, Ah.z, Ah.w, Bh1.x, Bh1.y);
            mma_bf16(c0[0], c0[1], c0[2], c0[3], Ah.x, Ah.y, Ah.z, Ah.w, Bl0.x, Bl0.y);
            mma_bf16(c1[0], c1[1], c1[2], c1[3], Ah.x, Ah.y, Ah.z, Ah.w, Bl1.x, Bl1.y);
            mma_bf16(c0[0], c0[1], c0[2], c0[3], Al.x, Al.y, Al.z, Al.w, Bh0.x, Bh0.y);
            mma_bf16(c1[0], c1[1], c1[2], c1[3], Al.x, Al.y, Al.z, Al.w, Bh1.x, Bh1.y);
        }

        // ---- scatter D frags to ex[b][row] (conflict-free: banks = 4b+r) ----
        {
            int r = (w << 4) + gid;
            int ba0 = ctib << 1;          // batch in nt=0
            ex[(ba0)     * PE + r]     = c0[0];
            ex[(ba0 + 1) * PE + r]     = c0[1];
            ex[(ba0)     * PE + r + 8] = c0[2];
            ex[(ba0 + 1) * PE + r + 8] = c0[3];
            int ba1 = 8 + (ctib << 1);    // batch in nt=1
            ex[(ba1)     * PE + r]     = c1[0];
            ex[(ba1 + 1) * PE + r]     = c1[1];
            ex[(ba1)     * PE + r + 8] = c1[2];
            ex[(ba1 + 1) * PE + r + 8] = c1[3];
        }
        __syncthreads();

        // ---- gates + state update + h write (v4, proven) ----
#pragma unroll
        for (int u = 0; u < 2; ++u) {
            int b = gb[u], c = gc[u];
            float iv = ex[b * PE + c]      + xv[u][0];
            float fv = ex[b * PE + 32 + c] + xv[u][1];
            float gv = ex[b * PE + 64 + c] + xv[u][2];
            float ov = ex[b * PE + 96 + c] + xv[u][3];
            float ig = fsig(iv), fg = fsig(fv), gg = ftanh_(gv), og = fsig(ov);
            cst[u] = fg * cst[u] + ig * gg;
            seq_out[((size_t)(b0 + b) * T_ + t) * H_ + (rank << 5) + c] = og * ftanh_(cst[u]);
        }

        // ---- cluster barrier: release h writes / acquire peers' ----
        asm volatile("barrier.cluster.arrive.aligned;\n\t"
                     "barrier.cluster.wait.aligned;\n\t" ::: "memory");
    }
}

// =====================================================================
// Launcher
// =====================================================================
extern "C" void kernel_launch(void* const* d_in, const int* in_sizes, int n_in,
                              void* d_out, int out_size)
{
    const float* x     = (const float*)d_in[0];
    const float* eWih0 = (const float*)d_in[1];
    const float* eWhh0 = (const float*)d_in[2];
    const float* ebih0 = (const float*)d_in[3];
    const float* ebhh0 = (const float*)d_in[4];
    const float* eWih1 = (const float*)d_in[5];
    const float* eWhh1 = (const float*)d_in[6];
    const float* ebih1 = (const float*)d_in[7];
    const float* ebhh1 = (const float*)d_in[8];
    const float* dWih0 = (const float*)d_in[9];
    const float* dWhh0 = (const float*)d_in[10];
    const float* dbih0 = (const float*)d_in[11];
    const float* dbhh0 = (const float*)d_in[12];
    const float* dWih1 = (const float*)d_in[13];
    const float* dWhh1 = (const float*)d_in[14];
    const float* dbih1 = (const float*)d_in[15];
    const float* dbhh1 = (const float*)d_in[16];
    const float* out_W = (const float*)d_in[17];
    const float* out_b = (const float*)d_in[18];
    float* out = (float*)d_out;

    void* p;
    cudaGetSymbolAddress(&p, g_xp); float* xp = (float*)p;
    cudaGetSymbolAddress(&p, g_s0); float* s0 = (float*)p;
    cudaGetSymbolAddress(&p, g_s1); float* s1 = (float*)p;

    cudaFuncSetAttribute(lstm_rec, cudaFuncAttributeMaxDynamicSharedMemorySize, REC_SMEM);

    dim3 blk(256);
    dim3 gXP(G_ / 64, BT_ / 128);   // N=1024 tiles x M tiles
    dim3 gPR(I_ / 64, BT_ / 128);   // projection N=64

    // encoder layer 0 (K = I = 64)
    gemm_abt_bias<<<gXP, blk>>>(x, eWih0, ebih0, ebhh0, xp, BT_, G_, I_);
    lstm_rec<<<128, blk, REC_SMEM>>>(eWhh0, xp, s0);
    // encoder layer 1 (K = H)
    gemm_abt_bias<<<gXP, blk>>>(s0, eWih1, ebih1, ebhh1, xp, BT_, G_, H_);
    lstm_rec<<<128, blk, REC_SMEM>>>(eWhh1, xp, s1);
    // decoder layer 0
    gemm_abt_bias<<<gXP, blk>>>(s1, dWih0, dbih0, dbhh0, xp, BT_, G_, H_);
    lstm_rec<<<128, blk, REC_SMEM>>>(dWhh0, xp, s0);
    // decoder layer 1
    gemm_abt_bias<<<gXP, blk>>>(s0, dWih1, dbih1, dbhh1, xp, BT_, G_, H_);
    lstm_rec<<<128, blk, REC_SMEM>>>(dWhh1, xp, s1);
    // output projection (N = I = 64, K = H)
    gemm_abt_bias<<<gPR, blk>>>(s1, out_W, out_b, nullptr, out, BT_, I_, H_);
}

// round 16
// speedup vs baseline: 2.0585x; 1.2074x over previous
#include <cuda_runtime.h>
#include <cuda_bf16.h>
#include <cstdint>
#include <cstddef>

// Problem constants
#define B_  256
#define T_  512
#define I_  64
#define H_  256
#define G_  1024            // 4*H
#define BT_ (B_ * T_)       // 131072

// -------- scratch (device globals; no allocation allowed) --------
__device__ float g_xp[(size_t)BT_ * G_];   // gate pre-activations for current layer
__device__ float g_s0[(size_t)BT_ * H_];   // layer output sequence (ping)
__device__ float g_s1[(size_t)BT_ * H_];   // layer output sequence (pong)

// ---------------- packed f32x2 helpers (GEMM kernel) ----------------
__device__ __forceinline__ unsigned long long pack2(float lo, float hi) {
    unsigned long long r;
    asm("mov.b64 %0, {%1, %2};" : "=l"(r)
        : "r"(__float_as_uint(lo)), "r"(__float_as_uint(hi)));
    return r;
}
__device__ __forceinline__ void fma2(unsigned long long& d,
                                     unsigned long long a, unsigned long long b) {
    asm("fma.rn.f32x2 %0, %1, %2, %0;" : "+l"(d) : "l"(a), "l"(b));
}
__device__ __forceinline__ float2 unpack2(unsigned long long v) {
    unsigned lo, hi;
    asm("mov.b64 {%0, %1}, %2;" : "=r"(lo), "=r"(hi) : "l"(v));
    return make_float2(__uint_as_float(lo), __uint_as_float(hi));
}

// =====================================================================
// GEMM v2 (R12-passing): double-buffered, register-prefetch, occ 3.
// (unchanged this round for clean rec attribution)
// =====================================================================
#define APITCH 132
#define BPITCH 68

__global__ void __launch_bounds__(256, 3)
gemm_abt_bias(const float* __restrict__ A, const float* __restrict__ Bm,
              const float* __restrict__ bias1, const float* __restrict__ bias2,
              float* __restrict__ C, int M, int N, int K)
{
    __shared__ float As[2][16 * APITCH];
    __shared__ float Bs[2][16 * BPITCH];

    const int tid = threadIdx.x;
    const int m0  = blockIdx.y * 128;
    const int n0  = blockIdx.x * 64;
    const int ty8 = (tid >> 4) * 8;
    const int tx4 = (tid & 15) * 4;

    const int lm = tid >> 2;
    const int lk = (tid & 3) << 2;

    const float* pA0 = &A[(size_t)(m0 + lm) * K + lk];
    const float* pA1 = &A[(size_t)(m0 + 64 + lm) * K + lk];
    const float* pB  = &Bm[(size_t)(n0 + lm) * K + lk];

    unsigned long long acc2[4][4];
#pragma unroll
    for (int p = 0; p < 4; ++p)
#pragma unroll
        for (int j = 0; j < 4; ++j) acc2[p][j] = 0ULL;

    const int ntile = K >> 4;

    float4 ra0 = *(const float4*)pA0;
    float4 ra1 = *(const float4*)pA1;
    float4 rb  = *(const float4*)pB;
    {
        float* as = As[0];
        float* bs = Bs[0];
        as[(lk + 0) * APITCH + lm]      = ra0.x;
        as[(lk + 1) * APITCH + lm]      = ra0.y;
        as[(lk + 2) * APITCH + lm]      = ra0.z;
        as[(lk + 3) * APITCH + lm]      = ra0.w;
        as[(lk + 0) * APITCH + 64 + lm] = ra1.x;
        as[(lk + 1) * APITCH + 64 + lm] = ra1.y;
        as[(lk + 2) * APITCH + 64 + lm] = ra1.z;
        as[(lk + 3) * APITCH + 64 + lm] = ra1.w;
        bs[(lk + 0) * BPITCH + lm] = rb.x;
        bs[(lk + 1) * BPITCH + lm] = rb.y;
        bs[(lk + 2) * BPITCH + lm] = rb.z;
        bs[(lk + 3) * BPITCH + lm] = rb.w;
    }
    __syncthreads();

    for (int kt = 0; kt < ntile; ++kt) {
        const bool more = (kt + 1) < ntile;
        if (more) {
            int off = (kt + 1) << 4;
            ra0 = *(const float4*)(pA0 + off);
            ra1 = *(const float4*)(pA1 + off);
            rb  = *(const float4*)(pB  + off);
        }

        const float* as = As[kt & 1];
        const float* bs = Bs[kt & 1];
#pragma unroll
        for (int kk = 0; kk < 16; ++kk) {
            ulonglong2 a01 = *(const ulonglong2*)&as[kk * APITCH + ty8];
            ulonglong2 a23 = *(const ulonglong2*)&as[kk * APITCH + ty8 + 4];
            float4 bv = *(const float4*)&bs[kk * BPITCH + tx4];
            unsigned long long am[4] = {a01.x, a01.y, a23.x, a23.y};
            float br[4] = {bv.x, bv.y, bv.z, bv.w};
#pragma unroll
            for (int j = 0; j < 4; ++j) {
                unsigned long long bp = pack2(br[j], br[j]);
#pragma unroll
                for (int p = 0; p < 4; ++p) fma2(acc2[p][j], am[p], bp);
            }
        }

        if (more) {
            float* asn = As[(kt + 1) & 1];
            float* bsn = Bs[(kt + 1) & 1];
            asn[(lk + 0) * APITCH + lm]      = ra0.x;
            asn[(lk + 1) * APITCH + lm]      = ra0.y;
            asn[(lk + 2) * APITCH + lm]      = ra0.z;
            asn[(lk + 3) * APITCH + lm]      = ra0.w;
            asn[(lk + 0) * APITCH + 64 + lm] = ra1.x;
            asn[(lk + 1) * APITCH + 64 + lm] = ra1.y;
            asn[(lk + 2) * APITCH + 64 + lm] = ra1.z;
            asn[(lk + 3) * APITCH + 64 + lm] = ra1.w;
            bsn[(lk + 0) * BPITCH + lm] = rb.x;
            bsn[(lk + 1) * BPITCH + lm] = rb.y;
            bsn[(lk + 2) * BPITCH + lm] = rb.z;
            bsn[(lk + 3) * BPITCH + lm] = rb.w;
            __syncthreads();
        }
    }

    float bvv[4];
#pragma unroll
    for (int j = 0; j < 4; ++j) {
        float b = bias1[n0 + tx4 + j];
        if (bias2) b += bias2[n0 + tx4 + j];
        bvv[j] = b;
    }
#pragma unroll
    for (int p = 0; p < 4; ++p) {
        float4 o0, o1;
        float2 u0 = unpack2(acc2[p][0]);
        float2 u1 = unpack2(acc2[p][1]);
        float2 u2 = unpack2(acc2[p][2]);
        float2 u3 = unpack2(acc2[p][3]);
        o0.x = u0.x + bvv[0]; o0.y = u1.x + bvv[1]; o0.z = u2.x + bvv[2]; o0.w = u3.x + bvv[3];
        o1.x = u0.y + bvv[0]; o1.y = u1.y + bvv[1]; o1.z = u2.y + bvv[2]; o1.w = u3.y + bvv[3];
        *(float4*)&C[(size_t)(m0 + ty8 + 2 * p)     * N + n0 + tx4] = o0;
        *(float4*)&C[(size_t)(m0 + ty8 + 2 * p + 1) * N + n0 + tx4] = o1;
    }
}

// =====================================================================
// Recurrent LSTM scan v10: HMMA step-GEMM (R15) + DSMEM h-exchange.
//   The epilogue publishes h directly into every cluster CTA's B-frag
//   buffers (bf16 hi/lo, final m16n8k16 .col frag layout) via
//   mapa + st.shared::cluster -- no global round-trip, no consumer-side
//   staging/conversion. B frags double-buffered by t parity:
//   MMA(t) reads buf[t&1]; epilogue(t) writes buf[(t+1)&1]; the end-of-
//   step cluster barrier (release/acquire) separates epochs, so a CTA
//   racing one step ahead only ever writes the buffer nobody reads.
// Fragment mappings (PTX m16n8k16, row.col) unchanged from R15:
//   A reg r: row = gid + (r&1)*8, k = ctib*2 + (r>>1)*8 (+kt*16)
//   B word:  idx = ((kt*2 + b>>3) << 6) + (((b&7)*4 + jp&3) << 1) + (jp>>2)
//            where kglobal = kt*16 + jp*2 (+0/1 in bf16x2), jp = (kglobal&15)>>1
//   C reg r: row = gid + (r>>1)*8, n = ctib*2 + (r&1)
// =====================================================================
#define PE 132
#define AFH_OFF  0
#define AFL_OFF  65536
#define BFH_OFF  131072              // 2 buffers x 8192 B
#define BFL_OFF  147456              // 2 buffers x 8192 B
#define EX_OFF   163840
#define REC_SMEM (EX_OFF + 16 * PE * 4)   // 172288 B

__device__ __forceinline__ uint32_t smem_u32(const void* p) {
    uint32_t a;
    asm("{ .reg .u64 t; cvta.to.shared.u64 t, %1; cvt.u32.u64 %0, t; }"
        : "=r"(a) : "l"(p));
    return a;
}
__device__ __forceinline__ uint32_t bfpack(float a, float b) {
    __nv_bfloat162 t = __floats2bfloat162_rn(a, b);
    return *reinterpret_cast<uint32_t*>(&t);
}
__device__ __forceinline__ void mma_bf16(float& c0, float& c1, float& c2, float& c3,
                                         uint32_t a0, uint32_t a1, uint32_t a2, uint32_t a3,
                                         uint32_t b0, uint32_t b1) {
    asm volatile(
        "mma.sync.aligned.m16n8k16.row.col.f32.bf16.bf16.f32 "
        "{%0,%1,%2,%3}, {%4,%5,%6,%7}, {%8,%9}, {%0,%1,%2,%3};"
        : "+f"(c0), "+f"(c1), "+f"(c2), "+f"(c3)
        : "r"(a0), "r"(a1), "r"(a2), "r"(a3), "r"(b0), "r"(b1));
}
__device__ __forceinline__ void st_cluster_u32(uint32_t laddr, int rrank, uint32_t val) {
    uint32_t ra;
    asm("mapa.shared::cluster.u32 %0, %1, %2;" : "=r"(ra) : "r"(laddr), "r"(rrank));
    asm volatile("st.shared::cluster.u32 [%0], %1;" :: "r"(ra), "r"(val) : "memory");
}
__device__ __forceinline__ float fsig(float x) {
    x = fminf(fmaxf(x, -30.f), 30.f);
    return __fdividef(1.f, 1.f + __expf(-x));
}
__device__ __forceinline__ float ftanh_(float x) {
    x = fminf(fmaxf(x, -15.f), 15.f);
    float e = __expf(-2.f * x);
    return __fdividef(1.f - e, 1.f + e);
}

__global__ void __cluster_dims__(8, 1, 1) __launch_bounds__(256, 1)
lstm_rec(const float* __restrict__ Whh, const float* __restrict__ xpg,
         float* __restrict__ seq_out)
{
    extern __shared__ __align__(16) char smem[];
    uint32_t* AFH = (uint32_t*)(smem + AFH_OFF);   // [8w][16kt][32lane][4reg]
    uint32_t* AFL = (uint32_t*)(smem + AFL_OFF);
    float*    ex  = (float*)(smem + EX_OFF);       // [16 b][PE rows]

    const int tid  = threadIdx.x;
    const int w    = tid >> 5;
    const int lane = tid & 31;
    const int gid  = lane >> 2;
    const int ctib = lane & 3;
    const int rank = blockIdx.x & 7;
    const int b0   = (blockIdx.x >> 3) * 16;
    const uint32_t smb = smem_u32(smem);

    // ---- build W fragment arrays once (hi/lo bf16 split) ----
    for (int i = tid; i < 16384; i += 256) {
        int reg = i & 3, ln = (i >> 2) & 31, kt = (i >> 7) & 15, ww = i >> 11;
        int g = ln >> 2, cb = ln & 3;
        int m  = ww * 16 + g + ((reg & 1) << 3);
        int k0 = kt * 16 + cb * 2 + ((reg >> 1) << 3);
        int gr = ((m >> 5) << 8) + (rank << 5) + (m & 31);
        float w0 = __ldg(&Whh[(size_t)gr * H_ + k0]);
        float w1 = __ldg(&Whh[(size_t)gr * H_ + k0 + 1]);
        __nv_bfloat16 h0 = __float2bfloat16(w0);
        __nv_bfloat16 h1 = __float2bfloat16(w1);
        AFH[i] = bfpack(__bfloat162float(h0), __bfloat162float(h1));
        AFL[i] = bfpack(w0 - __bfloat162float(h0), w1 - __bfloat162float(h1));
    }
    // zero B frag buffer 0 ONLY (t=0 state; buffer 1 is written by
    // peers' t=0 epilogues and must not be touched here)
    for (int i = tid; i < 2048; i += 256) {
        ((uint32_t*)(smem + BFH_OFF))[i] = 0u;
        ((uint32_t*)(smem + BFL_OFF))[i] = 0u;
    }

    // gate-epilogue mapping: idx = b*32 + c  (c == lane for both u)
    int gb[2];
#pragma unroll
    for (int u = 0; u < 2; ++u) gb[u] = (tid + (u << 8)) >> 5;
    float cst[2] = {0.f, 0.f};

    __syncthreads();

    for (int t = 0; t < T_; ++t) {
        // ---- xp prefetch (independent of h) ----
        float xv[2][4];
#pragma unroll
        for (int u = 0; u < 2; ++u)
#pragma unroll
            for (int g = 0; g < 4; ++g)
                xv[u][g] = __ldg(&xpg[((size_t)(b0 + gb[u]) * T_ + t) * G_ +
                                      (g << 8) + (rank << 5) + lane]);

        // ---- MMA: 16 k-tiles x (hi*hi + hi*lo + lo*hi), fp32 acc ----
        const uint32_t* BH = (const uint32_t*)(smem + BFH_OFF + ((t & 1) << 13));
        const uint32_t* BL = (const uint32_t*)(smem + BFL_OFF + ((t & 1) << 13));
        float c0[4] = {0.f, 0.f, 0.f, 0.f};   // nt = 0
        float c1[4] = {0.f, 0.f, 0.f, 0.f};   // nt = 1
#pragma unroll
        for (int kt = 0; kt < 16; ++kt) {
            uint4 Ah = ((const uint4*)AFH)[(w << 4 | kt) * 32 + lane];
            uint4 Al = ((const uint4*)AFL)[(w << 4 | kt) * 32 + lane];
            uint2 Bh0 = ((const uint2*)BH)[((kt << 1) | 0) * 32 + lane];
            uint2 Bh1 = ((const uint2*)BH)[((kt << 1) | 1) * 32 + lane];
            uint2 Bl0 = ((const uint2*)BL)[((kt << 1) | 0) * 32 + lane];
            uint2 Bl1 = ((const uint2*)BL)[((kt << 1) | 1) * 32 + lane];
            mma_bf16(c0[0], c0[1], c0[2], c0[3], Ah.x, Ah.y, Ah.z, Ah.w, Bh0.x, Bh0.y);
            mma_bf16(c1[0], c1[1], c1[2], c1[3], Ah.x, Ah.y, Ah.z, Ah.w, Bh1.x, Bh1.y);
            mma_bf16(c0[0], c0[1], c0[2], c0[3], Ah.x, Ah.y, Ah.z, Ah.w, Bl0.x, Bl0.y);
            mma_bf16(c1[0], c1[1], c1[2], c1[3], Ah.x, Ah.y, Ah.z, Ah.w, Bl1.x, Bl1.y);
            mma_bf16(c0[0], c0[1], c0[2], c0[3], Al.x, Al.y, Al.z, Al.w, Bh0.x, Bh0.y);
            mma_bf16(c1[0], c1[1], c1[2], c1[3], Al.x, Al.y, Al.z, Al.w, Bh1.x, Bh1.y);
        }

        // ---- scatter D frags to ex[b][row] (conflict-free) ----
        {
            int r = (w << 4) + gid;
            int ba0 = ctib << 1;
            ex[(ba0)     * PE + r]     = c0[0];
            ex[(ba0 + 1) * PE + r]     = c0[1];
            ex[(ba0)     * PE + r + 8] = c0[2];
            ex[(ba0 + 1) * PE + r + 8] = c0[3];
            int ba1 = 8 + (ctib << 1);
            ex[(ba1)     * PE + r]     = c1[0];
            ex[(ba1 + 1) * PE + r]     = c1[1];
            ex[(ba1)     * PE + r + 8] = c1[2];
            ex[(ba1 + 1) * PE + r + 8] = c1[3];
        }
        __syncthreads();

        // ---- gates + state + h write + DSMEM B-frag publish ----
        const uint32_t nbuf = ((t + 1) & 1) << 13;
#pragma unroll
        for (int u = 0; u < 2; ++u) {
            int b = gb[u];
            float iv = ex[b * PE + lane]      + xv[u][0];
            float fv = ex[b * PE + 32 + lane] + xv[u][1];
            float gv = ex[b * PE + 64 + lane] + xv[u][2];
            float ov = ex[b * PE + 96 + lane] + xv[u][3];
            float ig = fsig(iv), fg = fsig(fv), gg = ftanh_(gv), og = fsig(ov);
            cst[u] = fg * cst[u] + ig * gg;
            float hval = og * ftanh_(cst[u]);
            seq_out[((size_t)(b0 + b) * T_ + t) * H_ + (rank << 5) + lane] = hval;

            // split + pack pair (even c, odd c) and publish to all 8 CTAs
            __nv_bfloat16 bh = __float2bfloat16(hval);
            float rem = hval - __bfloat162float(bh);
            __nv_bfloat16 bl = __float2bfloat16(rem);
            uint32_t own = (uint32_t)__bfloat16_as_ushort(bh) |
                           ((uint32_t)__bfloat16_as_ushort(bl) << 16);
            uint32_t nb = __shfl_down_sync(0xffffffffu, own, 1);
            uint32_t hw = (own & 0xffffu) | (nb << 16);          // (hi_even, hi_odd)
            uint32_t lw = (own >> 16) | (nb & 0xffff0000u);      // (lo_even, lo_odd)
            uint32_t lw_o = __shfl_up_sync(0xffffffffu, lw, 1);  // deliver to odd lane

            int kglob = (rank << 5) + (lane & 30);
            int kt2 = kglob >> 4;
            int jp  = (kglob & 15) >> 1;
            int fidx = (((kt2 << 1) + (b >> 3)) << 6) +
                       ((((b & 7) << 2) + (jp & 3)) << 1) + (jp >> 2);
            uint32_t val, laddr;
            if (lane & 1) { val = lw_o; laddr = smb + BFL_OFF + nbuf + (fidx << 2); }
            else          { val = hw;   laddr = smb + BFH_OFF + nbuf + (fidx << 2); }
#pragma unroll
            for (int rr = 0; rr < 8; ++rr) st_cluster_u32(laddr, rr, val);
        }

        // ---- cluster barrier: release DSMEM stores / acquire peers' ----
        asm volatile("barrier.cluster.arrive.aligned;\n\t"
                     "barrier.cluster.wait.aligned;\n\t" ::: "memory");
    }
}

// =====================================================================
// Launcher
// =====================================================================
extern "C" void kernel_launch(void* const* d_in, const int* in_sizes, int n_in,
                              void* d_out, int out_size)
{
    const float* x     = (const float*)d_in[0];
    const float* eWih0 = (const float*)d_in[1];
    const float* eWhh0 = (const float*)d_in[2];
    const float* ebih0 = (const float*)d_in[3];
    const float* ebhh0 = (const float*)d_in[4];
    const float* eWih1 = (const float*)d_in[5];
    const float* eWhh1 = (const float*)d_in[6];
    const float* ebih1 = (const float*)d_in[7];
    const float* ebhh1 = (const float*)d_in[8];
    const float* dWih0 = (const float*)d_in[9];
    const float* dWhh0 = (const float*)d_in[10];
    const float* dbih0 = (const float*)d_in[11];
    const float* dbhh0 = (const float*)d_in[12];
    const float* dWih1 = (const float*)d_in[13];
    const float* dWhh1 = (const float*)d_in[14];
    const float* dbih1 = (const float*)d_in[15];
    const float* dbhh1 = (const float*)d_in[16];
    const float* out_W = (const float*)d_in[17];
    const float* out_b = (const float*)d_in[18];
    float* out = (float*)d_out;

    void* p;
    cudaGetSymbolAddress(&p, g_xp); float* xp = (float*)p;
    cudaGetSymbolAddress(&p, g_s0); float* s0 = (float*)p;
    cudaGetSymbolAddress(&p, g_s1); float* s1 = (float*)p;

    cudaFuncSetAttribute(lstm_rec, cudaFuncAttributeMaxDynamicSharedMemorySize, REC_SMEM);

    dim3 blk(256);
    dim3 gXP(G_ / 64, BT_ / 128);   // N=1024 tiles x M tiles
    dim3 gPR(I_ / 64, BT_ / 128);   // projection N=64

    // encoder layer 0 (K = I = 64)
    gemm_abt_bias<<<gXP, blk>>>(x, eWih0, ebih0, ebhh0, xp, BT_, G_, I_);
    lstm_rec<<<128, blk, REC_SMEM>>>(eWhh0, xp, s0);
    // encoder layer 1 (K = H)
    gemm_abt_bias<<<gXP, blk>>>(s0, eWih1, ebih1, ebhh1, xp, BT_, G_, H_);
    lstm_rec<<<128, blk, REC_SMEM>>>(eWhh1, xp, s1);
    // decoder layer 0
    gemm_abt_bias<<<gXP, blk>>>(s1, dWih0, dbih0, dbhh0, xp, BT_, G_, H_);
    lstm_rec<<<128, blk, REC_SMEM>>>(dWhh0, xp, s0);
    // decoder layer 1
    gemm_abt_bias<<<gXP, blk>>>(s0, dWih1, dbih1, dbhh1, xp, BT_, G_, H_);
    lstm_rec<<<128, blk, REC_SMEM>>>(dWhh1, xp, s1);
    // output projection (N = I = 64, K = H)
    gemm_abt_bias<<<gPR, blk>>>(s1, out_W, out_b, nullptr, out, BT_, I_, H_);
}